// round 10
// baseline (speedup 1.0000x reference)
#include <cuda_runtime.h>
#include <cuda_fp16.h>
#include <cstdint>

// C[b] = A[b](1024x64) @ B[b](64x1024), fp32, b in [0,24).
// fp16 mma.sync m16n8k16 (fp32 accum), warp tile 32x64, permuted-B epilogue
// (STG.128). Round 10: CTA shrunk to 64x128 / 128 threads -> 4 CTAs/SM
// (4 independent barrier domains; phases interleave across CTAs).

#define M_DIM 1024
#define N_DIM 1024
#define K_DIM 64
#define BATCH 24
#define THREADS 128

#define SMEM_A 0
#define SMEM_B 8192
#define SMEM_TOTAL 24576

#define SW128(o) ((o) ^ (((o) >> 3) & 0x70))

__device__ __forceinline__ uint32_t smem_u32(const void* p) {
    uint32_t a;
    asm("{ .reg .u64 t; cvta.to.shared.u64 t, %1; cvt.u32.u64 %0, t; }"
        : "=r"(a) : "l"(p));
    return a;
}

__device__ __forceinline__ void ldsm_x4(uint32_t* r, uint32_t addr) {
    asm volatile("ldmatrix.sync.aligned.m8n8.x4.shared.b16 {%0,%1,%2,%3}, [%4];"
                 : "=r"(r[0]), "=r"(r[1]), "=r"(r[2]), "=r"(r[3])
                 : "r"(addr));
}

__device__ __forceinline__ void mma_fp16(float* c, const uint32_t* a,
                                         uint32_t b0, uint32_t b1) {
    asm volatile(
        "mma.sync.aligned.m16n8k16.row.col.f32.f16.f16.f32 "
        "{%0,%1,%2,%3}, {%4,%5,%6,%7}, {%8,%9}, {%0,%1,%2,%3};"
        : "+f"(c[0]), "+f"(c[1]), "+f"(c[2]), "+f"(c[3])
        : "r"(a[0]), "r"(a[1]), "r"(a[2]), "r"(a[3]), "r"(b0), "r"(b1));
}

__device__ __forceinline__ uint32_t packh2(float a, float b) {
    uint32_t r;
    asm("{ .reg .f16 lo, hi;\n\t"
        "  cvt.rn.f16.f32 lo, %1;\n\t"
        "  cvt.rn.f16.f32 hi, %2;\n\t"
        "  mov.b32 %0, {lo, hi}; }"
        : "=r"(r) : "f"(a), "f"(b));
    return r;
}

// Column permutation within a 64-col warp block (see round 9).
__device__ __forceinline__ int bperm(int gb) {
    const int ni = (((gb >> 4) & 3) << 1) | ((gb >> 1) & 1);
    const int tq = (gb >> 2) & 3;
    return ni * 8 + tq * 2 + (gb & 1);
}

__global__ void __launch_bounds__(THREADS, 4)
bmm_fp16_kernel(const float* __restrict__ A,
                const float* __restrict__ B,
                float* __restrict__ C) {
    extern __shared__ __align__(1024) char smem[];
    const uint32_t smem_base = smem_u32(smem);
    const int tid = threadIdx.x;
    const int wid = tid >> 5;
    const int lid = tid & 31;

    const int bz   = blockIdx.z;
    const int row0 = blockIdx.y * 64;
    const int col0 = blockIdx.x * 128;

    const float* __restrict__ Ab = A + (size_t)bz * M_DIM * K_DIM;
    const float* __restrict__ Bb = B + (size_t)bz * K_DIM * N_DIM;
    float*       __restrict__ Cb = C + (size_t)bz * M_DIM * N_DIM;

    // ---- A tile: [64 m][64 k] fp32 -> fp16 smem (128B rows, SW128) ----
    // 1024 float4s, 8 per thread.
#pragma unroll
    for (int i = 0; i < 8; i++) {
        const int f = tid + i * THREADS;
        const int r = f >> 4;
        const int q = f & 15;
        float4 v = *reinterpret_cast<const float4*>(
            &Ab[(size_t)(row0 + r) * K_DIM + q * 4]);
        uint2 h = make_uint2(packh2(v.x, v.y), packh2(v.z, v.w));
        const uint32_t off = SW128((uint32_t)(r * 128 + q * 8));
        *reinterpret_cast<uint2*>(smem + SMEM_A + off) = h;
    }

    // ---- B tile: global [64 k][128 n] -> smem BT[perm(n)][k] fp16 (SW128) ----
    // Thread owns column n = tid, all 64 k (8 groups of 8).
    {
        const int n = tid;
        const int srow = (n & 64) + bperm(n & 63);
        const float* bcol = Bb + col0 + n;
#pragma unroll
        for (int k8 = 0; k8 < 8; k8++) {
            float v[8];
#pragma unroll
            for (int j = 0; j < 8; j++)
                v[j] = bcol[(size_t)(k8 * 8 + j) * N_DIM];
            uint4 h;
            h.x = packh2(v[0], v[1]); h.y = packh2(v[2], v[3]);
            h.z = packh2(v[4], v[5]); h.w = packh2(v[6], v[7]);
            const uint32_t off = SW128((uint32_t)(srow * 128 + k8 * 16));
            *reinterpret_cast<uint4*>(smem + SMEM_B + off) = h;
        }
    }

    __syncthreads();

    // ---- warp tiling: warp_m = wid&1 (32 rows), warp_n = wid>>1 (64 cols) ----
    const int warp_m = wid & 1;
    const int warp_n = wid >> 1;
    const int g = lid >> 3;
    const int r8 = lid & 7;
    const int a_row_l = warp_m * 32 + (g & 1) * 8 + r8;
    const int a_kb_l  = (g >> 1) * 16;
    const int b_row_l = warp_n * 64 + (g >> 1) * 8 + r8;
    const int b_kb_l  = (g & 1) * 16;

    float acc[2][8][4];
#pragma unroll
    for (int mi = 0; mi < 2; mi++)
#pragma unroll
        for (int ni = 0; ni < 8; ni++)
#pragma unroll
            for (int j = 0; j < 4; j++) acc[mi][ni][j] = 0.0f;

#pragma unroll
    for (int ks = 0; ks < 4; ks++) {
        uint32_t af[2][4];
        ldsm_x4(af[0], smem_base + SMEM_A +
                       SW128((uint32_t)(a_row_l * 128 + ks * 32 + a_kb_l)));
        ldsm_x4(af[1], smem_base + SMEM_A +
                       SW128((uint32_t)((a_row_l + 16) * 128 + ks * 32 + a_kb_l)));
        uint32_t bf[8][2];
#pragma unroll
        for (int nq = 0; nq < 4; nq++) {
            uint32_t rr[4];
            ldsm_x4(rr, smem_base + SMEM_B +
                        SW128((uint32_t)((b_row_l + nq * 16) * 128 + ks * 32 + b_kb_l)));
            bf[nq * 2 + 0][0] = rr[0]; bf[nq * 2 + 0][1] = rr[1];
            bf[nq * 2 + 1][0] = rr[2]; bf[nq * 2 + 1][1] = rr[3];
        }
#pragma unroll
        for (int mi = 0; mi < 2; mi++)
#pragma unroll
            for (int ni = 0; ni < 8; ni++)
                mma_fp16(acc[mi][ni], af[mi], bf[ni][0], bf[ni][1]);
    }

    // ---- epilogue: contiguous STG.128 per thread (permuted B) ----
    const int tq = lid & 3;
    const int tr = lid >> 2;
#pragma unroll
    for (int mi = 0; mi < 2; mi++) {
        const int rbase = row0 + warp_m * 32 + mi * 16 + tr;
        float* c0 = &Cb[(size_t)rbase * N_DIM + col0 + warp_n * 64 + tq * 4];
        float* c1 = c0 + 8 * N_DIM;
#pragma unroll
        for (int c = 0; c < 4; c++) {
            float4 v0 = make_float4(acc[mi][2 * c][0], acc[mi][2 * c][1],
                                    acc[mi][2 * c + 1][0], acc[mi][2 * c + 1][1]);
            float4 v1 = make_float4(acc[mi][2 * c][2], acc[mi][2 * c][3],
                                    acc[mi][2 * c + 1][2], acc[mi][2 * c + 1][3]);
            *reinterpret_cast<float4*>(c0 + c * 16) = v0;
            *reinterpret_cast<float4*>(c1 + c * 16) = v1;
        }
    }
}

extern "C" void kernel_launch(void* const* d_in, const int* in_sizes, int n_in,
                              void* d_out, int out_size) {
    const float* A = (const float*)d_in[0];   // [2,12,1024,64]
    const float* B = (const float*)d_in[1];   // [2,12,64,1024]
    float* C = (float*)d_out;                 // [2,12,1024,1024]

    cudaFuncSetAttribute(bmm_fp16_kernel,
                         cudaFuncAttributeMaxDynamicSharedMemorySize, SMEM_TOTAL);
    dim3 grid(N_DIM / 128, M_DIM / 64, BATCH);  // (8, 16, 24)
    bmm_fp16_kernel<<<grid, THREADS, SMEM_TOTAL>>>(A, B, C);
}

// round 11
// speedup vs baseline: 1.0447x; 1.0447x over previous
#include <cuda_runtime.h>
#include <cuda_fp16.h>
#include <cstdint>

// C[b] = A[b](1024x64) @ B[b](64x1024), fp32, b in [0,24).
// fp16 mma.sync m16n8k16 (fp32 accum), CTA 128m x 256n (two 128-wide n-tiles),
// warp tile 32x64, permuted-B epilogue (STG.128).
// Round 11: A loaded once per 2 tiles; B tile-2 prefetched raw via cp.async
// into smem staging during tile-1 compute; B loads vectorized (LDG.128).

#define M_DIM 1024
#define N_DIM 1024
#define K_DIM 64
#define BATCH 24
#define THREADS 256

#define SMEM_A      0        // 128 x 64 fp16, SW128 rows (16 KB)
#define SMEM_B      16384    // 128 x 64 fp16 transposed+permuted (16 KB)
#define SMEM_BSTAGE 32768    // 64 x 128 fp32 raw staging (32 KB)
#define SMEM_TOTAL  65536

#define SW128(o) ((o) ^ (((o) >> 3) & 0x70))

__device__ __forceinline__ uint32_t smem_u32(const void* p) {
    uint32_t a;
    asm("{ .reg .u64 t; cvta.to.shared.u64 t, %1; cvt.u32.u64 %0, t; }"
        : "=r"(a) : "l"(p));
    return a;
}

__device__ __forceinline__ void cp16(uint32_t dst, const void* src) {
    asm volatile("cp.async.cg.shared.global [%0], [%1], 16;"
                 :: "r"(dst), "l"(src));
}

__device__ __forceinline__ void ldsm_x4(uint32_t* r, uint32_t addr) {
    asm volatile("ldmatrix.sync.aligned.m8n8.x4.shared.b16 {%0,%1,%2,%3}, [%4];"
                 : "=r"(r[0]), "=r"(r[1]), "=r"(r[2]), "=r"(r[3])
                 : "r"(addr));
}

__device__ __forceinline__ void mma_fp16(float* c, const uint32_t* a,
                                         uint32_t b0, uint32_t b1) {
    asm volatile(
        "mma.sync.aligned.m16n8k16.row.col.f32.f16.f16.f32 "
        "{%0,%1,%2,%3}, {%4,%5,%6,%7}, {%8,%9}, {%0,%1,%2,%3};"
        : "+f"(c[0]), "+f"(c[1]), "+f"(c[2]), "+f"(c[3])
        : "r"(a[0]), "r"(a[1]), "r"(a[2]), "r"(a[3]), "r"(b0), "r"(b1));
}

__device__ __forceinline__ uint32_t packh2(float a, float b) {
    uint32_t r;
    asm("{ .reg .f16 lo, hi;\n\t"
        "  cvt.rn.f16.f32 lo, %1;\n\t"
        "  cvt.rn.f16.f32 hi, %2;\n\t"
        "  mov.b32 %0, {lo, hi}; }"
        : "=r"(r) : "f"(a), "f"(b));
    return r;
}

// Column permutation within a 64-col warp block (round 9).
__device__ __forceinline__ int bperm(int gb) {
    const int ni = (((gb >> 4) & 3) << 1) | ((gb >> 1) & 1);
    const int tq = (gb >> 2) & 3;
    return ni * 8 + tq * 2 + (gb & 1);
}

// Convert a 4n x 8k fp32 block (in registers as 8 float4 rows over k) to fp16
// and store transposed+permuted into B smem. nq = n-quad index, kb = k-group.
__device__ __forceinline__ void store_b_block(char* smem, int nq, int kb,
                                              const float4* v) {
#pragma unroll
    for (int e = 0; e < 4; e++) {   // n within quad
        const int n = nq * 4 + e;
        const int srow = (n & 64) + bperm(n & 63);
        const float* vf = reinterpret_cast<const float*>(v);
        uint4 h;
        h.x = packh2(vf[0 * 4 + e], vf[1 * 4 + e]);
        h.y = packh2(vf[2 * 4 + e], vf[3 * 4 + e]);
        h.z = packh2(vf[4 * 4 + e], vf[5 * 4 + e]);
        h.w = packh2(vf[6 * 4 + e], vf[7 * 4 + e]);
        const uint32_t off = SW128((uint32_t)(srow * 128 + kb * 16));
        *reinterpret_cast<uint4*>(smem + SMEM_B + off) = h;
    }
}

__global__ void __launch_bounds__(THREADS, 2)
bmm_fp16_kernel(const float* __restrict__ A,
                const float* __restrict__ B,
                float* __restrict__ C) {
    extern __shared__ __align__(1024) char smem[];
    const uint32_t smem_base = smem_u32(smem);
    const int tid = threadIdx.x;
    const int wid = tid >> 5;
    const int lid = tid & 31;

    const int bz    = blockIdx.z;
    const int row0  = blockIdx.y * 128;
    const int col0a = blockIdx.x * 256;          // tile 1
    const int col0b = col0a + 128;               // tile 2

    const float* __restrict__ Ab = A + (size_t)bz * M_DIM * K_DIM;
    const float* __restrict__ Bb = B + (size_t)bz * K_DIM * N_DIM;
    float*       __restrict__ Cb = C + (size_t)bz * M_DIM * N_DIM;

    // ---- A tile: [128 m][64 k] fp32 -> fp16 smem (128B rows, SW128) ----
#pragma unroll
    for (int i = 0; i < 8; i++) {
        const int f = tid + i * THREADS;
        const int r = f >> 4;
        const int q = f & 15;
        float4 v = *reinterpret_cast<const float4*>(
            &Ab[(size_t)(row0 + r) * K_DIM + q * 4]);
        uint2 h = make_uint2(packh2(v.x, v.y), packh2(v.z, v.w));
        const uint32_t off = SW128((uint32_t)(r * 128 + q * 8));
        *reinterpret_cast<uint2*>(smem + SMEM_A + off) = h;
    }

    // ---- B tile 1: vectorized LDG.128 [k][n], reg-transpose -> fp16 smem ----
    // Thread t: nq = t&31 (n-quad), kb = t>>5 (k-group of 8). 8 LDG.128.
    const int nq = tid & 31;
    const int kb = tid >> 5;
    {
        float4 v[8];
#pragma unroll
        for (int j = 0; j < 8; j++)
            v[j] = *reinterpret_cast<const float4*>(
                &Bb[(size_t)(kb * 8 + j) * N_DIM + col0a + nq * 4]);
        store_b_block(smem, nq, kb, v);
    }

    // ---- prefetch raw fp32 B tile 2 into staging via cp.async ----
    {
#pragma unroll
        for (int i = 0; i < 8; i++) {
            const int c = tid + i * THREADS;       // 16B chunk id, 0..2047
            const int r = c >> 5;                  // k row
            const int o = (c & 31) * 16;           // byte offset in 512B row
            cp16(smem_base + SMEM_BSTAGE + r * 512 + o,
                 (const char*)(Bb + (size_t)r * N_DIM + col0b) + o);
        }
        asm volatile("cp.async.commit_group;" ::: "memory");
    }

    __syncthreads();

    // ---- warp tiling (fixed across both tiles) ----
    const int warp_m = wid & 3;
    const int warp_n = wid >> 2;
    const int g = lid >> 3;
    const int r8 = lid & 7;
    const int a_row_l = warp_m * 32 + (g & 1) * 8 + r8;
    const int a_kb_l  = (g >> 1) * 16;
    const int b_row_l = warp_n * 64 + (g >> 1) * 8 + r8;
    const int b_kb_l  = (g & 1) * 16;
    const int tq = lid & 3;
    const int tr = lid >> 2;

#pragma unroll
    for (int t = 0; t < 2; t++) {
        float acc[2][8][4];
#pragma unroll
        for (int mi = 0; mi < 2; mi++)
#pragma unroll
            for (int ni = 0; ni < 8; ni++)
#pragma unroll
                for (int j = 0; j < 4; j++) acc[mi][ni][j] = 0.0f;

#pragma unroll
        for (int ks = 0; ks < 4; ks++) {
            uint32_t af[2][4];
            ldsm_x4(af[0], smem_base + SMEM_A +
                           SW128((uint32_t)(a_row_l * 128 + ks * 32 + a_kb_l)));
            ldsm_x4(af[1], smem_base + SMEM_A +
                           SW128((uint32_t)((a_row_l + 16) * 128 + ks * 32 + a_kb_l)));
            uint32_t bf[8][2];
#pragma unroll
            for (int nqf = 0; nqf < 4; nqf++) {
                uint32_t rr[4];
                ldsm_x4(rr, smem_base + SMEM_B +
                            SW128((uint32_t)((b_row_l + nqf * 16) * 128 + ks * 32 + b_kb_l)));
                bf[nqf * 2 + 0][0] = rr[0]; bf[nqf * 2 + 0][1] = rr[1];
                bf[nqf * 2 + 1][0] = rr[2]; bf[nqf * 2 + 1][1] = rr[3];
            }
#pragma unroll
            for (int mi = 0; mi < 2; mi++)
#pragma unroll
                for (int ni = 0; ni < 8; ni++)
                    mma_fp16(acc[mi][ni], af[mi], bf[ni][0], bf[ni][1]);
        }

        // ---- epilogue: contiguous STG.128 (permuted B) ----
        const int col0 = t == 0 ? col0a : col0b;
#pragma unroll
        for (int mi = 0; mi < 2; mi++) {
            const int rbase = row0 + warp_m * 32 + mi * 16 + tr;
            float* c0 = &Cb[(size_t)rbase * N_DIM + col0 + warp_n * 64 + tq * 4];
            float* c1 = c0 + 8 * N_DIM;
#pragma unroll
            for (int c = 0; c < 4; c++) {
                float4 v0 = make_float4(acc[mi][2 * c][0], acc[mi][2 * c][1],
                                        acc[mi][2 * c + 1][0], acc[mi][2 * c + 1][1]);
                float4 v1 = make_float4(acc[mi][2 * c][2], acc[mi][2 * c][3],
                                        acc[mi][2 * c + 1][2], acc[mi][2 * c + 1][3]);
                *reinterpret_cast<float4*>(c0 + c * 16) = v0;
                *reinterpret_cast<float4*>(c1 + c * 16) = v1;
            }
        }

        // ---- between tiles: convert staged B2 into the fp16 B buffer ----
        if (t == 0) {
            asm volatile("cp.async.wait_group 0;" ::: "memory");
            __syncthreads();   // compute-1 B reads done AND staging complete
            float4 v[8];
#pragma unroll
            for (int j = 0; j < 8; j++)
                v[j] = *reinterpret_cast<const float4*>(
                    smem + SMEM_BSTAGE + (kb * 8 + j) * 512 + nq * 16);
            store_b_block(smem, nq, kb, v);
            __syncthreads();
        }
    }
}

extern "C" void kernel_launch(void* const* d_in, const int* in_sizes, int n_in,
                              void* d_out, int out_size) {
    const float* A = (const float*)d_in[0];   // [2,12,1024,64]
    const float* B = (const float*)d_in[1];   // [2,12,64,1024]
    float* C = (float*)d_out;                 // [2,12,1024,1024]

    cudaFuncSetAttribute(bmm_fp16_kernel,
                         cudaFuncAttributeMaxDynamicSharedMemorySize, SMEM_TOTAL);
    dim3 grid(N_DIM / 256, M_DIM / 128, BATCH);  // (4, 8, 24)
    bmm_fp16_kernel<<<grid, THREADS, SMEM_TOTAL>>>(A, B, C);
}